// round 14
// baseline (speedup 1.0000x reference)
#include <cuda_runtime.h>
#include <cuda_bf16.h>
#include <cstdint>

#define FULLMASK 0xffffffffu

// ---------------------------------------------------------------------------
// Compare-exchange: `down ? fmaxf : fminf` with a pass-uniform runtime
// predicate is the ptxas idiom for a single predicated FMNMX (alu pipe).
// down == true  -> lower index keeps MAX (descending order).
// Cost: exactly 2 alu ops per CE, 1 per output. This is the alu-pipe floor.
// ---------------------------------------------------------------------------
__device__ __forceinline__ void ce_dir(float& a, float& b, bool down) {
    float hi = down ? fmaxf(a, b) : fminf(a, b);   // FMNMX  P
    float lo = down ? fminf(a, b) : fmaxf(a, b);   // FMNMX !P
    a = hi; b = lo;
}

// ---------------------------------------------------------------------------
// Phase 1: Batcher odd-even mergesort of the 32 in-register values.
// 191 comparators vs 240 for the bitonic K=2..32 stages (-20%).
// Sorts descending when down==true. All indices compile-time after unroll.
// ---------------------------------------------------------------------------
template<int LO, int N, int R>
__device__ __forceinline__ void oem_merge(float (&v)[32], bool down) {
    constexpr int M = 2 * R;
    if constexpr (M < N) {
        oem_merge<LO,     N, M>(v, down);
        oem_merge<LO + R, N, M>(v, down);
        #pragma unroll
        for (int i = LO + R; i + R < LO + N; i += M)
            ce_dir(v[i], v[i + R], down);
    } else {
        ce_dir(v[LO], v[LO + R], down);
    }
}

template<int LO, int N>
__device__ __forceinline__ void oem_sort(float (&v)[32], bool down) {
    if constexpr (N > 1) {
        oem_sort<LO,         N / 2>(v, down);
        oem_sort<LO + N / 2, N / 2>(v, down);
        oem_merge<LO, N, 1>(v, down);
    }
}

// ---------------------------------------------------------------------------
// Phase 2: bitonic merge stages K = 64 .. 1024 across lanes.
// Element index idx = lane*32 + r. Direction bit (idx & K) is a lane bit
// (runtime, uniform across each pass -> one FSETP, reused).
// ---------------------------------------------------------------------------

// In-register pass: distance J < 32. 16 CEs, 32 FMNMX.
template<int K, int J>
__device__ __forceinline__ void pass_reg(float (&v)[32], int lane) {
    const bool down = ((lane & (K >> 5)) == 0);
    #pragma unroll
    for (int r = 0; r < 32; r++)
        if ((r & J) == 0)
            ce_dir(v[r], v[r | J], down);
}

// Cross-lane pass: distance J >= 32 -> shfl.xor, each element keeps one of
// {min,max}: 1 SHFL (mio) + 1 predicated FMNMX (alu) per element.
template<int K, int J>
__device__ __forceinline__ void pass_shfl(float (&v)[32], int lane) {
    constexpr int MASK = J >> 5;
    const bool down     = ((lane & (K >> 5)) == 0);
    const bool keep_max = (down == ((lane & MASK) == 0));
    #pragma unroll
    for (int r = 0; r < 32; r++) {
        float p = __shfl_xor_sync(FULLMASK, v[r], MASK);
        v[r] = keep_max ? fmaxf(v[r], p) : fminf(v[r], p);
    }
}

template<int K, int J>
__device__ __forceinline__ void merge_steps(float (&v)[32], int lane) {
    if constexpr (J >= 32) pass_shfl<K, J>(v, lane);
    else                   pass_reg <K, J>(v, lane);
    if constexpr (J > 1) merge_steps<K, (J >> 1)>(v, lane);
}

template<int K>
__device__ __forceinline__ void bitonic_stage(float (&v)[32], int lane) {
    merge_steps<K, (K >> 1)>(v, lane);
    if constexpr (K < 1024) bitonic_stage<(K << 1)>(v, lane);
}

__global__ void GlobalRankPooling_kernel(const float* __restrict__ x,
                                         const float* __restrict__ w,
                                         const float* __restrict__ bias,
                                         float* __restrict__ out,
                                         int C, int rows) {
    const int lane = threadIdx.x & 31;
    const int row  = blockIdx.x * (blockDim.x >> 5) + (threadIdx.x >> 5);
    if (row >= rows) return;
    const int c = row % C;

    // ---- Load: fully coalesced float4. Initial placement is irrelevant
    // (the sort only cares about the multiset of values).
    float v[32];
    const float4* xp = reinterpret_cast<const float4*>(x) + (size_t)row * 256;
    #pragma unroll
    for (int i = 0; i < 8; i++) {
        float4 t = xp[i * 32 + lane];
        v[4 * i + 0] = t.x; v[4 * i + 1] = t.y;
        v[4 * i + 2] = t.z; v[4 * i + 3] = t.w;
    }

    // ---- Phase 1: per-lane 32-element sort (Batcher OEMS, 191 CEs).
    // Even lanes descending, odd lanes ascending — exactly the post-state of
    // bitonic stage K=32, so stage K=64 can consume it directly.
    oem_sort<0, 32>(v, (lane & 1) == 0);

    // ---- Phase 2: cross-lane bitonic merges K=64..1024 (descending).
    bitonic_stage<64>(v, lane);
    // Now v[r] on `lane` = sorted_desc[lane*32 + r].

    // ---- Dot with weight row in sorted-rank order. Each lane reads its own
    // 128B line; the 8MB weight tensor stays L2-resident across 32 batches.
    const float4* wp = reinterpret_cast<const float4*>(w) + (size_t)c * 256 + lane * 8;
    float acc = 0.0f;
    #pragma unroll
    for (int i = 0; i < 8; i++) {
        float4 t = wp[i];
        acc += t.x * v[4 * i + 0] + t.y * v[4 * i + 1]
             + t.z * v[4 * i + 2] + t.w * v[4 * i + 3];
    }

    // ---- Warp reduce + bias.
    #pragma unroll
    for (int m = 16; m; m >>= 1) acc += __shfl_xor_sync(FULLMASK, acc, m);
    if (lane == 0) out[row] = acc + __ldg(bias + c);
}

extern "C" void kernel_launch(void* const* d_in, const int* in_sizes, int n_in,
                              void* d_out, int out_size) {
    const float* x    = (const float*)d_in[0];   // (B, C, H, W) fp32
    const float* w    = (const float*)d_in[1];   // (C, 1, S)    fp32
    const float* bias = (const float*)d_in[2];   // (C,)         fp32
    float* out = (float*)d_out;                  // (B, C, 1)    fp32

    const int C    = in_sizes[2];                // 2048
    const int rows = in_sizes[0] / 1024;         // B*C = 65536 (S = 1024)

    const int warps_per_block = 8;               // 256 threads
    const int blocks = (rows + warps_per_block - 1) / warps_per_block;
    GlobalRankPooling_kernel<<<blocks, 256>>>(x, w, bias, out, C, rows);
}

// round 15
// speedup vs baseline: 1.3508x; 1.3508x over previous
#include <cuda_runtime.h>
#include <cuda_bf16.h>
#include <cstdint>

#define FULLMASK 0xffffffffu

// ---------------------------------------------------------------------------
// Runtime-direction compare-exchange, "A1" form.
//
// Codegen model (validated R13/R14): a LONE ternary `p ? fmaxf : fminf`
// becomes one predicated FMNMX (alu pipe). Two ternaries over the same (a,b)
// get CSE'd into FMNMX+FMNMX+SEL+SEL. So: produce exactly ONE output via a
// lone ternary, and recover the second as s - first on the fma pipe (FADD).
// Cost: 1 alu + 2 fma, 3 issue slots, zero selects, direction fully runtime.
//
// down == true  -> a (lower index) keeps MAX (descending order).
// ---------------------------------------------------------------------------
__device__ __forceinline__ void ce_a1(float& a, float& b, bool down) {
    float s  = a + b;                              // FADD  (fma pipe)
    float lo = down ? fminf(a, b) : fmaxf(a, b);   // FMNMX P (alu pipe)
    a = s - lo;                                    // FADD  (fma pipe)
    b = lo;
}

// ---------------------------------------------------------------------------
// Phase 1: Batcher odd-even mergesort of the 32 in-register values
// (191 comparators). Direction runtime-uniform per lane; ce_a1 makes that
// free. All register indices compile-time after unroll.
// ---------------------------------------------------------------------------
template<int LO, int N, int R>
__device__ __forceinline__ void oem_merge(float (&v)[32], bool down) {
    constexpr int M = 2 * R;
    if constexpr (M < N) {
        oem_merge<LO,     N, M>(v, down);
        oem_merge<LO + R, N, M>(v, down);
        #pragma unroll
        for (int i = LO + R; i + R < LO + N; i += M)
            ce_a1(v[i], v[i + R], down);
    } else {
        ce_a1(v[LO], v[LO + R], down);
    }
}

template<int LO, int N>
__device__ __forceinline__ void oem_sort(float (&v)[32], bool down) {
    if constexpr (N > 1) {
        oem_sort<LO,         N / 2>(v, down);
        oem_sort<LO + N / 2, N / 2>(v, down);
        oem_merge<LO, N, 1>(v, down);
    }
}

// ---------------------------------------------------------------------------
// Phase 2: bitonic merge stages K = 64 .. 1024 across lanes.
// Element index idx = lane*32 + r; direction bit (idx & K) is a lane bit
// (runtime, uniform across each pass).
// ---------------------------------------------------------------------------

// In-register pass: distance J < 32. 16 CEs -> 16 alu + 32 fma.
template<int K, int J>
__device__ __forceinline__ void pass_reg(float (&v)[32], int lane) {
    const bool down = ((lane & (K >> 5)) == 0);
    #pragma unroll
    for (int r = 0; r < 32; r++)
        if ((r & J) == 0)
            ce_a1(v[r], v[r | J], down);
}

// Cross-lane pass: distance J >= 32 -> shfl.xor. Each element keeps one of
// {min,max}: 1 SHFL (mio) + 1 lone-ternary predicated FMNMX (alu).
template<int K, int J>
__device__ __forceinline__ void pass_shfl(float (&v)[32], int lane) {
    constexpr int MASK = J >> 5;
    const bool down     = ((lane & (K >> 5)) == 0);
    const bool keep_max = (down == ((lane & MASK) == 0));
    #pragma unroll
    for (int r = 0; r < 32; r++) {
        float p = __shfl_xor_sync(FULLMASK, v[r], MASK);
        v[r] = keep_max ? fmaxf(v[r], p) : fminf(v[r], p);   // FMNMX P
    }
}

template<int K, int J>
__device__ __forceinline__ void merge_steps(float (&v)[32], int lane) {
    if constexpr (J >= 32) pass_shfl<K, J>(v, lane);
    else                   pass_reg <K, J>(v, lane);
    if constexpr (J > 1) merge_steps<K, (J >> 1)>(v, lane);
}

template<int K>
__device__ __forceinline__ void bitonic_stage(float (&v)[32], int lane) {
    merge_steps<K, (K >> 1)>(v, lane);
    if constexpr (K < 1024) bitonic_stage<(K << 1)>(v, lane);
}

__global__ void GlobalRankPooling_kernel(const float* __restrict__ x,
                                         const float* __restrict__ w,
                                         const float* __restrict__ bias,
                                         float* __restrict__ out,
                                         int C, int rows) {
    const int lane = threadIdx.x & 31;
    const int row  = blockIdx.x * (blockDim.x >> 5) + (threadIdx.x >> 5);
    if (row >= rows) return;
    const int c = row % C;

    // ---- Load: fully coalesced float4. Initial placement is irrelevant
    // (the sort only cares about the multiset of values).
    float v[32];
    const float4* xp = reinterpret_cast<const float4*>(x) + (size_t)row * 256;
    #pragma unroll
    for (int i = 0; i < 8; i++) {
        float4 t = xp[i * 32 + lane];
        v[4 * i + 0] = t.x; v[4 * i + 1] = t.y;
        v[4 * i + 2] = t.z; v[4 * i + 3] = t.w;
    }

    // ---- Phase 1: per-lane 32-element Batcher sort (191 CEs).
    // Even lanes descending, odd ascending -> exactly the bitonic-stage-32
    // post-state that stage K=64 expects.
    oem_sort<0, 32>(v, (lane & 1) == 0);

    // ---- Phase 2: cross-lane bitonic merges K=64..1024 (descending).
    bitonic_stage<64>(v, lane);
    // Now v[r] on `lane` = sorted_desc[lane*32 + r].

    // ---- Dot with weight row in sorted-rank order. Each lane reads its own
    // 128B line; the 8MB weight tensor stays L2-resident across 32 batches.
    const float4* wp = reinterpret_cast<const float4*>(w) + (size_t)c * 256 + lane * 8;
    float acc = 0.0f;
    #pragma unroll
    for (int i = 0; i < 8; i++) {
        float4 t = wp[i];
        acc = fmaf(t.x, v[4 * i + 0], acc);
        acc = fmaf(t.y, v[4 * i + 1], acc);
        acc = fmaf(t.z, v[4 * i + 2], acc);
        acc = fmaf(t.w, v[4 * i + 3], acc);
    }

    // ---- Warp reduce + bias.
    #pragma unroll
    for (int m = 16; m; m >>= 1) acc += __shfl_xor_sync(FULLMASK, acc, m);
    if (lane == 0) out[row] = acc + __ldg(bias + c);
}

extern "C" void kernel_launch(void* const* d_in, const int* in_sizes, int n_in,
                              void* d_out, int out_size) {
    const float* x    = (const float*)d_in[0];   // (B, C, H, W) fp32
    const float* w    = (const float*)d_in[1];   // (C, 1, S)    fp32
    const float* bias = (const float*)d_in[2];   // (C,)         fp32
    float* out = (float*)d_out;                  // (B, C, 1)    fp32

    const int C    = in_sizes[2];                // 2048
    const int rows = in_sizes[0] / 1024;         // B*C = 65536 (S = 1024)

    const int warps_per_block = 8;               // 256 threads
    const int blocks = (rows + warps_per_block - 1) / warps_per_block;
    GlobalRankPooling_kernel<<<blocks, 256>>>(x, w, bias, out, C, rows);
}